// round 17
// baseline (speedup 1.0000x reference)
#include <cuda_runtime.h>
#include <cuda_fp16.h>
#include <cstdint>
#include <math.h>

// ---------------- Problem dims (fixed) ----------------
#define T_TOK   8192
#define D_DIM   2048
#define M_DIM   1024
#define E_NUM   8
#define NCOPIES (T_TOK*2)

// ---------------- Scratch ----------------
__device__ int   g_route[16];            // [0..8) counts, [8..16) cursor
__device__ int   g_offsets[E_NUM + 1];
__device__ int   g_expert[NCOPIES];
__device__ float g_weight[NCOPIES];
__device__ int   g_pos[NCOPIES];
__device__ int   g_row2tok[NCOPIES];

__device__ __half g_xh[(size_t)T_TOK * D_DIM];
__device__ __half g_w1[(size_t)E_NUM * D_DIM * 2 * M_DIM];   // [E][K=D][gate|up] k-major
__device__ __half g_w2[(size_t)E_NUM * M_DIM * D_DIM];       // [E][K=M][N=D]    k-major
__device__ __half g_inter[(size_t)NCOPIES * M_DIM];
__device__ __half g_outsorted[(size_t)NCOPIES * D_DIM];

// ---------------- helpers ----------------
__device__ __forceinline__ uint32_t smem_u32(const void* p) {
    uint32_t a;
    asm("{ .reg .u64 t; cvta.to.shared.u64 t, %1; cvt.u32.u64 %0, t; }" : "=r"(a) : "l"(p));
    return a;
}
__device__ __forceinline__ void cp_async16(uint32_t dst, const void* src) {
    asm volatile("cp.async.cg.shared.global [%0], [%1], 16;" :: "r"(dst), "l"(src) : "memory");
}
__device__ __forceinline__ void cp_commit() {
    asm volatile("cp.async.commit_group;" ::: "memory");
}
__device__ __forceinline__ void cp_wait2() {
    asm volatile("cp.async.wait_group 2;" ::: "memory");
}
__device__ __forceinline__ void cp_wait_all() {
    asm volatile("cp.async.wait_group 0;" ::: "memory");
}
__device__ __forceinline__ void ldm_x4(uint32_t& r0, uint32_t& r1, uint32_t& r2, uint32_t& r3, uint32_t addr) {
    asm volatile("ldmatrix.sync.aligned.m8n8.x4.shared.b16 {%0,%1,%2,%3}, [%4];"
                 : "=r"(r0), "=r"(r1), "=r"(r2), "=r"(r3) : "r"(addr));
}
__device__ __forceinline__ void ldm_x4_t(uint32_t& r0, uint32_t& r1, uint32_t& r2, uint32_t& r3, uint32_t addr) {
    asm volatile("ldmatrix.sync.aligned.m8n8.x4.trans.shared.b16 {%0,%1,%2,%3}, [%4];"
                 : "=r"(r0), "=r"(r1), "=r"(r2), "=r"(r3) : "r"(addr));
}
__device__ __forceinline__ void mma_f16(float* c, const uint32_t* a, uint32_t b0, uint32_t b1) {
    asm volatile(
        "mma.sync.aligned.m16n8k16.row.col.f32.f16.f16.f32 "
        "{%0,%1,%2,%3}, {%4,%5,%6,%7}, {%8,%9}, {%0,%1,%2,%3};"
        : "+f"(c[0]), "+f"(c[1]), "+f"(c[2]), "+f"(c[3])
        : "r"(a[0]), "r"(a[1]), "r"(a[2]), "r"(a[3]), "r"(b0), "r"(b1));
}

// ---------------- routing ----------------
__global__ void router_k(const float* __restrict__ x, const float* __restrict__ wg) {
    extern __shared__ float wgs[];   // 64 KB
    int tx = threadIdx.x;
    for (int idx = tx; idx < D_DIM * E_NUM; idx += 256) {
        int d = idx >> 3;
        int e = idx & 7;
        wgs[e * D_DIM + d] = wg[idx];
    }
    __syncthreads();

    int warp = tx >> 5;
    int lane = tx & 31;
    int t = blockIdx.x * 8 + warp;
    if (t >= T_TOK) return;
    const float4* xr4 = reinterpret_cast<const float4*>(x + (size_t)t * D_DIM);
    __half* xh = g_xh + (size_t)t * D_DIM;

    float acc[E_NUM];
    for (int e = 0; e < E_NUM; e++) acc[e] = 0.f;

    for (int k = 0; k < D_DIM / 128; k++) {
        int q = k * 32 + lane;
        float4 v = xr4[q];
        __half2 h0 = __floats2half2_rn(v.x, v.y);
        __half2 h1 = __floats2half2_rn(v.z, v.w);
        uint2 u;
        u.x = *reinterpret_cast<uint32_t*>(&h0);
        u.y = *reinterpret_cast<uint32_t*>(&h1);
        *reinterpret_cast<uint2*>(xh + q * 4) = u;
        for (int e = 0; e < E_NUM; e++) {
            float4 w = *reinterpret_cast<const float4*>(&wgs[e * D_DIM + q * 4]);
            acc[e] += v.x * w.x + v.y * w.y + v.z * w.z + v.w * w.w;
        }
    }
    for (int e = 0; e < E_NUM; e++) {
        for (int o = 16; o > 0; o >>= 1) acc[e] += __shfl_xor_sync(0xffffffffu, acc[e], o);
    }
    if (lane == 0) {
        int e0 = 0; float l0 = acc[0];
        for (int e = 1; e < E_NUM; e++) { if (acc[e] > l0) { l0 = acc[e]; e0 = e; } }
        int e1 = -1; float l1 = -INFINITY;
        for (int e = 0; e < E_NUM; e++) { if (e != e0 && acc[e] > l1) { l1 = acc[e]; e1 = e; } }
        float w0 = 1.f / (1.f + expf(l1 - l0));
        g_expert[t * 2 + 0] = e0;
        g_expert[t * 2 + 1] = e1;
        g_weight[t * 2 + 0] = w0;
        g_weight[t * 2 + 1] = 1.f - w0;
        atomicAdd(&g_route[e0], 1);
        atomicAdd(&g_route[e1], 1);
    }
}

__global__ void assign_k() {
    __shared__ int offs[E_NUM];
    if (threadIdx.x == 0) {
        int s = 0;
        for (int e = 0; e < E_NUM; e++) { offs[e] = s; s += g_route[e]; }
        if (blockIdx.x == 0) {
            int s2 = 0;
            for (int e = 0; e < E_NUM; e++) { g_offsets[e] = s2; s2 += g_route[e]; }
            g_offsets[E_NUM] = s2;
        }
    }
    __syncthreads();
    int i = blockIdx.x * blockDim.x + threadIdx.x;
    if (i >= NCOPIES) return;
    int e = g_expert[i];
    int lane = threadIdx.x & 31;
    int p = -1;
    for (int ee = 0; ee < E_NUM; ee++) {
        unsigned mask = __ballot_sync(0xffffffffu, e == ee);
        if (e == ee) {
            int leader = __ffs(mask) - 1;
            int rank = __popc(mask & ((1u << lane) - 1));
            int base = 0;
            if (lane == leader) base = atomicAdd(&g_route[8 + ee], __popc(mask));
            base = __shfl_sync(mask, base, leader);
            p = offs[ee] + base + rank;
        }
    }
    g_pos[i] = p;
    g_row2tok[p] = i >> 1;
}

// ---------------- weight conversion (single merged streaming kernel) ----------------
// blockIdx.y: 0..15 -> w1 (e*2+s), 16..23 -> w2 (e = y-16)
__global__ void convw_k(const float* __restrict__ wi0, const float* __restrict__ wi1,
                        const float* __restrict__ wo) {
    int y = blockIdx.y;
    size_t rem = ((size_t)blockIdx.x * 256 + threadIdx.x) * 8;   // < D*M = 2M elems
    const float* src;
    __half* dst;
    if (y < 16) {
        int e = y >> 1;
        int s = y & 1;
        src = (s ? wi1 : wi0) + (size_t)e * D_DIM * M_DIM + rem;
        int d = (int)(rem >> 10);
        int m = (int)(rem & 1023);
        dst = g_w1 + ((size_t)e * D_DIM + d) * 2048 + s * 1024 + m;
    } else {
        int e = y - 16;
        src = wo + (size_t)e * M_DIM * D_DIM + rem;
        dst = g_w2 + (size_t)e * M_DIM * D_DIM + rem;
    }
    float4 a = *reinterpret_cast<const float4*>(src);
    float4 b = *reinterpret_cast<const float4*>(src + 4);
    __half2 h0 = __floats2half2_rn(a.x, a.y);
    __half2 h1 = __floats2half2_rn(a.z, a.w);
    __half2 h2 = __floats2half2_rn(b.x, b.y);
    __half2 h3 = __floats2half2_rn(b.z, b.w);
    uint4 u;
    u.x = *reinterpret_cast<uint32_t*>(&h0);
    u.y = *reinterpret_cast<uint32_t*>(&h1);
    u.z = *reinterpret_cast<uint32_t*>(&h2);
    u.w = *reinterpret_cast<uint32_t*>(&h3);
    *reinterpret_cast<uint4*>(dst) = u;
}

// ---------------- mma.sync grouped GEMM (trans-B, persistent grid) ----------------
#define ROWB      80
#define A_BYTES   (128*ROWB)
#define B_ROWB    272
#define B_BYTES   (32*B_ROWB)
#define STG_BYTES (A_BYTES + B_BYTES)
#define NSTAGE    4
#define TILE_SMEM (NSTAGE*STG_BYTES)
#define SMEM_REQ  (TILE_SMEM + 512)
#define NPERSIST  296            // 2 CTAs x 148 SMs

__device__ __forceinline__ void load_stage(
    uint32_t sbase, int stg, int tx,
    const __half* A, const __half* Bw,
    const int* arow_tab, int aRowBase, int cnt,
    int bKbase, int nlo, int nhi, int KT, int k0)
{
    uint32_t s0 = sbase + (uint32_t)stg * STG_BYTES;
    for (int i = 0; i < 2; i++) {
        int id = tx + i * 256;
        int rowA = id >> 2;
        int cc = id & 3;
        int arow;
        if (arow_tab) {
            arow = arow_tab[rowA];
        } else {
            arow = aRowBase + ((rowA < cnt) ? rowA : (cnt - 1));
        }
        size_t goA = (size_t)arow * KT + k0 + cc * 8;
        cp_async16(s0 + (uint32_t)(rowA * ROWB + cc * 16), A + goA);
        int brow = id >> 4;
        int bc = id & 15;
        int ncol = (bc < 8) ? (nlo + bc * 8) : (nhi + (bc - 8) * 8);
        size_t goB = ((size_t)(bKbase + k0 + brow)) * 2048 + ncol;
        cp_async16(s0 + (uint32_t)(A_BYTES + brow * B_ROWB + bc * 16), Bw + goB);
    }
}

__device__ __forceinline__ void gemm_mainloop(
    uint32_t sbase, int tx,
    const __half* A, const __half* Bw,
    const int* arow_tab, int aRowBase, int cnt,
    int bKbase, int nlo, int nhi, int KT,
    float acc[4][4][4])
{
    const int NITER = KT / 32;
    int wid = tx >> 5;
    int lane = tx & 31;
    int wm = wid >> 2;
    int wn = wid & 3;
    int l15 = lane & 15;
    int l16 = lane >> 4;

    uint32_t aoff = (uint32_t)((wm * 64 + l15) * ROWB + l16 * 16);
    uint32_t boff = (uint32_t)(A_BYTES
                   + ((lane & 7) + ((lane >> 4) << 3)) * B_ROWB
                   + ((lane >> 3) & 1) * 16);

    load_stage(sbase, 0, tx, A, Bw, arow_tab, aRowBase, cnt, bKbase, nlo, nhi, KT, 0);
    cp_commit();
    load_stage(sbase, 1, tx, A, Bw, arow_tab, aRowBase, cnt, bKbase, nlo, nhi, KT, 32);
    cp_commit();

    for (int it = 0; it < NITER; it++) {
        if (it + 2 < NITER) {
            load_stage(sbase, (it + 2) % NSTAGE, tx, A, Bw,
                       arow_tab, aRowBase, cnt, bKbase, nlo, nhi, KT, (it + 2) * 32);
        }
        cp_commit();
        cp_wait2();
        __syncthreads();

        uint32_t s0 = sbase + (uint32_t)(it % NSTAGE) * STG_BYTES;
        for (int kk = 0; kk < 2; kk++) {
            uint32_t ah[4][4], bb[2][4];
            for (int mt = 0; mt < 4; mt++) {
                uint32_t ad = s0 + aoff + (uint32_t)(mt * 16 * ROWB + kk * 32);
                ldm_x4(ah[mt][0], ah[mt][1], ah[mt][2], ah[mt][3], ad);
            }
            for (int g = 0; g < 2; g++) {
                uint32_t bd = s0 + boff + (uint32_t)(kk * 16 * B_ROWB + wn * 64 + g * 32);
                ldm_x4_t(bb[g][0], bb[g][1], bb[g][2], bb[g][3], bd);
            }
            for (int mt = 0; mt < 4; mt++) {
                for (int nt = 0; nt < 4; nt++) {
                    int g = nt >> 1;
                    int p = nt & 1;
                    mma_f16(acc[mt][nt], ah[mt], bb[g][p], bb[g][p + 2]);
                }
            }
        }
    }
    cp_wait_all();   // drain in-flight cp.async before smem reuse by epilogue
}

// Expert tile lookup: given linear tile t and per-expert tile counts, find (e, local).
struct TileLoc { int e; int rowt; int col; };
__device__ __forceinline__ TileLoc locate_tile(int t, int ncols, int* cumt) {
    TileLoc L;
    int e = 0;
    while (t >= cumt[e + 1]) e++;
    int local = t - cumt[e];
    L.e = e;
    L.rowt = local / ncols;
    L.col = local % ncols;
    return L;
}

// GEMM1 persistent: silu-fused, N-cols = 16 (64 gate + 64 up each)
#define F1_STR 132
__global__ void __launch_bounds__(256, 2) gemm1_mma() {
    extern __shared__ char smraw[];
    uint32_t sbase = smem_u32(smraw);
    int* toks = reinterpret_cast<int*>(smraw + TILE_SMEM);
    int tx = threadIdx.x;

    __shared__ int cumt[E_NUM + 1];
    if (tx == 0) {
        int s = 0;
        for (int e = 0; e < E_NUM; e++) {
            cumt[e] = s;
            int cnt = g_offsets[e + 1] - g_offsets[e];
            s += ((cnt + 127) >> 7) * 16;
        }
        cumt[E_NUM] = s;
    }
    __syncthreads();
    int total = cumt[E_NUM];

    for (int t = blockIdx.x; t < total; t += NPERSIST) {
        TileLoc L = locate_tile(t, 16, cumt);
        int base = g_offsets[L.e];
        int cnt  = g_offsets[L.e + 1] - base;
        int row0 = L.rowt * 128;
        int col0g = L.col * 64;

        if (tx < 128) {
            int r = row0 + tx;
            toks[tx] = g_row2tok[base + ((r < cnt) ? r : (cnt - 1))];
        }
        __syncthreads();

        float acc[4][4][4];
        for (int a = 0; a < 4; a++)
            for (int b = 0; b < 4; b++)
                for (int c = 0; c < 4; c++) acc[a][b][c] = 0.f;

        gemm_mainloop(sbase, tx, g_xh, g_w1, toks, 0, cnt - row0,
                      L.e * D_DIM, col0g, 1024 + col0g, 2048, acc);

        __syncthreads();
        float* fbuf = reinterpret_cast<float*>(smraw);
        int wid = tx >> 5;
        int lane = tx & 31;
        int wm = wid >> 2;
        int wn = wid & 3;
        int qrow = lane >> 2;
        int qcol = lane & 3;
        for (int mt = 0; mt < 4; mt++) {
            for (int nt = 0; nt < 4; nt++) {
                int rl = wm * 64 + mt * 16 + qrow;
                int cl = wn * 32 + nt * 8 + qcol * 2;
                float* c = acc[mt][nt];
                *reinterpret_cast<float2*>(&fbuf[rl * F1_STR + cl])       = make_float2(c[0], c[1]);
                *reinterpret_cast<float2*>(&fbuf[(rl + 8) * F1_STR + cl]) = make_float2(c[2], c[3]);
            }
        }
        __syncthreads();
        for (int idx = tx; idx < 128 * 8; idx += 256) {
            int r = idx >> 3;
            int seg = idx & 7;
            if (row0 + r < cnt) {
                uint32_t outp[4];
                for (int j = 0; j < 4; j++) {
                    float g0 = fbuf[r * F1_STR + seg * 8 + 2 * j];
                    float g1 = fbuf[r * F1_STR + seg * 8 + 2 * j + 1];
                    float u0 = fbuf[r * F1_STR + 64 + seg * 8 + 2 * j];
                    float u1 = fbuf[r * F1_STR + 64 + seg * 8 + 2 * j + 1];
                    float v0 = g0 / (1.f + __expf(-g0)) * u0;
                    float v1 = g1 / (1.f + __expf(-g1)) * u1;
                    __half2 h = __floats2half2_rn(v0, v1);
                    outp[j] = *reinterpret_cast<uint32_t*>(&h);
                }
                uint4 v;
                v.x = outp[0]; v.y = outp[1]; v.z = outp[2]; v.w = outp[3];
                *reinterpret_cast<uint4*>(
                    &g_inter[(size_t)(base + row0 + r) * M_DIM + col0g + seg * 8]) = v;
            }
        }
        __syncthreads();   // protect smem before next tile's load_stage
    }
}

// GEMM2 persistent: N-cols = 16 (128 wide each)
#define E2_STR 136
__global__ void __launch_bounds__(256, 2) gemm2_mma() {
    extern __shared__ char smraw[];
    uint32_t sbase = smem_u32(smraw);
    int tx = threadIdx.x;

    __shared__ int cumt[E_NUM + 1];
    if (tx == 0) {
        int s = 0;
        for (int e = 0; e < E_NUM; e++) {
            cumt[e] = s;
            int cnt = g_offsets[e + 1] - g_offsets[e];
            s += ((cnt + 127) >> 7) * 16;
        }
        cumt[E_NUM] = s;
    }
    __syncthreads();
    int total = cumt[E_NUM];

    for (int t = blockIdx.x; t < total; t += NPERSIST) {
        TileLoc L = locate_tile(t, 16, cumt);
        int base = g_offsets[L.e];
        int cnt  = g_offsets[L.e + 1] - base;
        int row0 = L.rowt * 128;
        int col0 = L.col * 128;

        float acc[4][4][4];
        for (int a = 0; a < 4; a++)
            for (int b = 0; b < 4; b++)
                for (int c = 0; c < 4; c++) acc[a][b][c] = 0.f;

        gemm_mainloop(sbase, tx, g_inter, g_w2, (const int*)0,
                      base + row0, cnt - row0,
                      L.e * M_DIM, col0, col0 + 64, 1024, acc);

        __syncthreads();
        __half* buf = reinterpret_cast<__half*>(smraw);
        int wid = tx >> 5;
        int lane = tx & 31;
        int wm = wid >> 2;
        int wn = wid & 3;
        int qrow = lane >> 2;
        int qcol = lane & 3;
        for (int mt = 0; mt < 4; mt++) {
            for (int nt = 0; nt < 4; nt++) {
                int rl = wm * 64 + mt * 16 + qrow;
                int cl = wn * 32 + nt * 8 + qcol * 2;
                float* c = acc[mt][nt];
                __half2 v0 = __floats2half2_rn(c[0], c[1]);
                __half2 v1 = __floats2half2_rn(c[2], c[3]);
                *reinterpret_cast<__half2*>(&buf[rl * E2_STR + cl])       = v0;
                *reinterpret_cast<__half2*>(&buf[(rl + 8) * E2_STR + cl]) = v1;
            }
        }
        __syncthreads();
        for (int idx = tx; idx < 128 * 16; idx += 256) {
            int r = idx >> 4;
            int seg = idx & 15;
            if (row0 + r < cnt) {
                uint4 v = *reinterpret_cast<uint4*>(&buf[r * E2_STR + seg * 8]);
                *reinterpret_cast<uint4*>(
                    &g_outsorted[(size_t)(base + row0 + r) * D_DIM + col0 + seg * 8]) = v;
            }
        }
        __syncthreads();
    }
}

// ---------------- combine ----------------
__global__ void combine_k(float* __restrict__ out) {
    for (int tt = 0; tt < 2; tt++) {
        int t = blockIdx.x * 2 + tt;
        float w0 = g_weight[t * 2 + 0];
        float w1 = g_weight[t * 2 + 1];
        const __half* p0 = g_outsorted + (size_t)g_pos[t * 2 + 0] * D_DIM;
        const __half* p1 = g_outsorted + (size_t)g_pos[t * 2 + 1] * D_DIM;
        float* o = out + (size_t)t * D_DIM;
        int d = threadIdx.x * 8;
        uint4 ua = *reinterpret_cast<const uint4*>(p0 + d);
        uint4 ub = *reinterpret_cast<const uint4*>(p1 + d);
        const __half2* ha = reinterpret_cast<const __half2*>(&ua);
        const __half2* hb = reinterpret_cast<const __half2*>(&ub);
        float rr[8];
        for (int i = 0; i < 4; i++) {
            float2 fa = __half22float2(ha[i]);
            float2 fb = __half22float2(hb[i]);
            rr[2 * i + 0] = w0 * fa.x + w1 * fb.x;
            rr[2 * i + 1] = w0 * fa.y + w1 * fb.y;
        }
        *reinterpret_cast<float4*>(o + d)     = make_float4(rr[0], rr[1], rr[2], rr[3]);
        *reinterpret_cast<float4*>(o + d + 4) = make_float4(rr[4], rr[5], rr[6], rr[7]);
    }
}

// ---------------- launch ----------------
#define ROUTER_SMEM (E_NUM * D_DIM * 4)

extern "C" void kernel_launch(void* const* d_in, const int* in_sizes, int n_in,
                              void* d_out, int out_size) {
    const float* x   = (const float*)d_in[0];
    const float* wg  = (const float*)d_in[1];
    const float* wi0 = (const float*)d_in[2];
    const float* wi1 = (const float*)d_in[3];
    const float* wo  = (const float*)d_in[4];
    float* out = (float*)d_out;

    static void* route_addr = 0;
    if (!route_addr) {
        cudaGetSymbolAddress(&route_addr, g_route);
        cudaFuncSetAttribute(router_k, cudaFuncAttributeMaxDynamicSharedMemorySize, ROUTER_SMEM);
        cudaFuncSetAttribute(gemm1_mma, cudaFuncAttributeMaxDynamicSharedMemorySize, SMEM_REQ);
        cudaFuncSetAttribute(gemm2_mma, cudaFuncAttributeMaxDynamicSharedMemorySize, SMEM_REQ);
    }

    cudaMemsetAsync(route_addr, 0, 16 * sizeof(int), 0);
    router_k<<<T_TOK / 8, 256, ROUTER_SMEM>>>(x, wg);
    assign_k<<<NCOPIES / 256, 256>>>();

    convw_k<<<dim3((D_DIM * M_DIM) / (256 * 8), 24), 256>>>(wi0, wi1, wo);

    gemm1_mma<<<NPERSIST, 256, SMEM_REQ>>>();
    gemm2_mma<<<NPERSIST, 256, SMEM_REQ>>>();

    combine_k<<<T_TOK / 2, 256>>>(out);
}